// round 2
// baseline (speedup 1.0000x reference)
#include <cuda_runtime.h>
#include <cuda_bf16.h>
#include <math.h>

#define BB 64
#define TT 4096
#define FF 64
#define DHH 64
#define DGG 128
#define G3 384   // 3*DG

typedef unsigned long long u64;

// ---------------- scratch (device globals; no cudaMalloc allowed) ----------------
__device__ __align__(128) float g_gx_buf[(size_t)BB * TT * G3];   // 402.7 MB
__device__ __align__(128) float g_z_buf[(size_t)BB * TT * DGG];   // 134.2 MB
__device__ __align__(128) unsigned char g_mask[(size_t)BB * TT * FF]; // 16.7 MB canonical mask
__device__ double g_sum[FF];
__device__ double g_sumsq[FF];
__device__ double g_mcnt;
__device__ double g_loss;
__device__ int g_flag_byte;
__device__ int g_flag_half;

// ---------------- helpers ----------------
__device__ __forceinline__ u64 pk2(float lo, float hi) {
    u64 r; asm("mov.b64 %0, {%1, %2};" : "=l"(r) : "f"(lo), "f"(hi)); return r;
}
__device__ __forceinline__ float2 upk2(u64 v) {
    float2 r; asm("mov.b64 {%0, %1}, %2;" : "=f"(r.x), "=f"(r.y) : "l"(v)); return r;
}
// Blackwell packed fp32 FMA (SASS: FFMA2) — 2 MACs/lane/instr
__device__ __forceinline__ u64 fma2(u64 a, u64 b, u64 c) {
    u64 d; asm("fma.rn.f32x2 %0, %1, %2, %3;" : "=l"(d) : "l"(a), "l"(b), "l"(c)); return d;
}
__device__ __forceinline__ float gelu_exact(float a) {
    return 0.5f * a * (1.0f + erff(a * 0.70710678118654752440f));
}
__device__ __forceinline__ float sigm(float x) {
    return __fdividef(1.0f, 1.0f + __expf(-x));
}
__device__ __forceinline__ float tanh_fast(float x) {
    float s = copysignf(1.0f, x);
    float e = __expf(-2.0f * fabsf(x));
    return s * __fdividef(1.0f - e, 1.0f + e);
}

// ---------------- K0: reset accumulators (graph replays!) ----------------
__global__ void k_init() {
    int t = threadIdx.x;
    if (t < FF) { g_sum[t] = 0.0; g_sumsq[t] = 0.0; }
    if (t == FF) g_mcnt = 0.0;
    if (t == FF + 1) g_loss = 0.0;
    if (t == FF + 2) g_flag_byte = 0;
    if (t == FF + 3) g_flag_half = 0;
}

// ---------------- K0b: probe mask element width from bit patterns ----------------
// Safe read extent across all candidate dtypes: BB*TT*FF bytes (the minimum size).
__global__ __launch_bounds__(256) void k_probe(const unsigned int* __restrict__ m) {
    int byteF = 0, halfF = 0;
    size_t nwords = (size_t)BB * TT * FF / 4;
    for (size_t i = (size_t)blockIdx.x * blockDim.x + threadIdx.x; i < nwords;
         i += (size_t)gridDim.x * blockDim.x) {
        unsigned v = m[i];
        if (v == 0u || v == 1u || v == 0x3F800000u) continue;  // word-mode compatible
        bool b01 = true;
        #pragma unroll
        for (int k = 0; k < 4; k++) {
            unsigned bt = (v >> (8 * k)) & 0xFFu;
            if (bt > 1u) b01 = false;
        }
        if (b01) { byteF = 1; continue; }
        bool h16 = true;
        #pragma unroll
        for (int k = 0; k < 2; k++) {
            unsigned h = (v >> (16 * k)) & 0xFFFFu;
            if (h != 0u && h != 0x3F80u) h16 = false;
        }
        if (h16) { halfF = 1; continue; }
        byteF = 1;  // nonstandard byte values (e.g. 0xFF) -> byte mode
    }
    if (byteF) g_flag_byte = 1;
    if (halfF) g_flag_half = 1;
}

// ---------------- K0c: canonicalize mask to uint8 ----------------
__global__ __launch_bounds__(256) void k_mkconv(const void* __restrict__ m) {
    int bF = g_flag_byte, hF = g_flag_half;
    size_t N = (size_t)BB * TT * FF;
    for (size_t i = (size_t)blockIdx.x * blockDim.x + threadIdx.x; i < N;
         i += (size_t)gridDim.x * blockDim.x) {
        unsigned char r;
        if (bF)      r = (((const unsigned char*)m)[i] != 0);
        else if (hF) r = (((const unsigned short*)m)[i] != 0);
        else         r = (((const unsigned int*)m)[i] != 0);
        g_mask[i] = r;
    }
}

// ---------------- K1: per-feature sum / sumsq (for std) + mask count ----------------
__global__ __launch_bounds__(256) void k_stats(const float* __restrict__ x) {
    int tid = threadIdx.x;
    int f = tid & 63;
    int rg = tid >> 6; // 0..3
    float s = 0.f, q = 0.f; int mc = 0;
    for (int r = blockIdx.x * 4 + rg; r < BB * TT; r += gridDim.x * 4) {
        size_t gi = (size_t)r * FF + f;
        float v = x[gi];
        s += v;
        q = fmaf(v, v, q);
        mc += g_mask[gi] ? 1 : 0;
    }
    __shared__ float ss[256]; __shared__ float sq[256]; __shared__ int sm_[256];
    ss[tid] = s; sq[tid] = q; sm_[tid] = mc;
    __syncthreads();
    if (tid < 64) {
        double S = (double)ss[tid] + (double)ss[tid + 64] + (double)ss[tid + 128] + (double)ss[tid + 192];
        double Q = (double)sq[tid] + (double)sq[tid + 64] + (double)sq[tid + 128] + (double)sq[tid + 192];
        atomicAdd(&g_sum[f], S);
        atomicAdd(&g_sumsq[f], Q);
        sm_[tid] = sm_[tid] + sm_[tid + 64] + sm_[tid + 128] + sm_[tid + 192];
    }
    __syncthreads();
    if (tid == 0) {
        int tot = 0;
        for (int i = 0; i < 64; i++) tot += sm_[i];
        atomicAdd(&g_mcnt, (double)tot);
    }
}

// ---------------- K2: fused mask + stem + GELU + conv1d(k3,p1) + GELU + gx GEMM ----------------
// SMEM layout (floats)
#define E_W1   0        // 64x64  stem_w [f][d]
#define E_CW   4096     // 192x64 conv_w transposed [(i*3+k)][o]
#define E_WIH  16384    // 64x384 w_ih transposed [d][h]
#define E_SB   40960    // 64
#define E_CB   41024    // 64
#define E_BIH  41088    // 384
#define E_X    41472    // 66x64
#define E_H0   45696    // 66x64
#define E_H1   49920    // 64x65 (pad 65: conflict-free gemv reads)
#define E_TOT  54080    // floats -> 216320 bytes

__global__ __launch_bounds__(512, 1) void k_encoder(
    const float* __restrict__ x,
    const float* __restrict__ stem_w, const float* __restrict__ stem_b,
    const float* __restrict__ conv_w, const float* __restrict__ conv_b,
    const float* __restrict__ w_ih, const float* __restrict__ b_ih)
{
    extern __shared__ float smem[];
    int tid = threadIdx.x;

    // load weights once (persistent blocks)
    for (int i = tid; i < 4096; i += 512) smem[E_W1 + i] = stem_w[i];
    for (int i = tid; i < 12288; i += 512) {
        int o = i & 63, ik = i >> 6;               // ik = in*3+k
        smem[E_CW + i] = conv_w[o * 192 + ik];
    }
    for (int i = tid; i < 24576; i += 512) {
        int h = i % 384, d = i / 384;
        smem[E_WIH + i] = w_ih[h * 64 + d];
    }
    for (int i = tid; i < 64; i += 512) { smem[E_SB + i] = stem_b[i]; smem[E_CB + i] = conv_b[i]; }
    for (int i = tid; i < 384; i += 512) smem[E_BIH + i] = b_ih[i];
    __syncthreads();

    for (int tile = blockIdx.x; tile < BB * (TT / 64); tile += gridDim.x) {
        int b = tile >> 6;
        int t0 = (tile & 63) << 6;

        // load x rows [t0-1, t0+64], masked
        for (int i = tid; i < 66 * 64; i += 512) {
            int row = i >> 6, f = i & 63;
            int t = t0 - 1 + row;
            float v = 0.f;
            if (t >= 0 && t < TT) {
                size_t gi = ((size_t)b * TT + t) * FF + f;
                v = g_mask[gi] ? 0.f : x[gi];
            }
            smem[E_X + i] = v;
        }
        __syncthreads();

        // stem GEMM + GELU: h0[66][64]; boundary rows forced to 0 (conv zero-padding on h!)
        for (int q = tid; q < 66 * 16; q += 512) {
            int i = q >> 4, d4 = (q & 15) << 2;
            int t = t0 - 1 + i;
            float4 acc = *(const float4*)&smem[E_SB + d4];
            const float* xr = &smem[E_X + i * 64];
            #pragma unroll 16
            for (int f = 0; f < 64; f++) {
                float xv = xr[f];
                float4 w = *(const float4*)&smem[E_W1 + f * 64 + d4];
                acc.x = fmaf(xv, w.x, acc.x);
                acc.y = fmaf(xv, w.y, acc.y);
                acc.z = fmaf(xv, w.z, acc.z);
                acc.w = fmaf(xv, w.w, acc.w);
            }
            bool valid = (t >= 0) && (t < TT);
            float4 r;
            r.x = valid ? gelu_exact(acc.x) : 0.f;
            r.y = valid ? gelu_exact(acc.y) : 0.f;
            r.z = valid ? gelu_exact(acc.z) : 0.f;
            r.w = valid ? gelu_exact(acc.w) : 0.f;
            *(float4*)&smem[E_H0 + i * 64 + d4] = r;
        }
        __syncthreads();

        // conv1d k=3 + GELU: h1[64][64] (row pad 65)
        for (int q = tid; q < 64 * 16; q += 512) {
            int tl = q >> 4, o4 = (q & 15) << 2;
            float4 acc = *(const float4*)&smem[E_CB + o4];
            const float* h0a = &smem[E_H0 + tl * 64];
            const float* h0b = h0a + 64;
            const float* h0c = h0a + 128;
            #pragma unroll 8
            for (int i = 0; i < 64; i++) {
                float a0 = h0a[i], a1 = h0b[i], a2 = h0c[i];
                float4 w0 = *(const float4*)&smem[E_CW + (i * 3 + 0) * 64 + o4];
                float4 w1 = *(const float4*)&smem[E_CW + (i * 3 + 1) * 64 + o4];
                float4 w2 = *(const float4*)&smem[E_CW + (i * 3 + 2) * 64 + o4];
                acc.x = fmaf(a0, w0.x, fmaf(a1, w1.x, fmaf(a2, w2.x, acc.x)));
                acc.y = fmaf(a0, w0.y, fmaf(a1, w1.y, fmaf(a2, w2.y, acc.y)));
                acc.z = fmaf(a0, w0.z, fmaf(a1, w1.z, fmaf(a2, w2.z, acc.z)));
                acc.w = fmaf(a0, w0.w, fmaf(a1, w1.w, fmaf(a2, w2.w, acc.w)));
            }
            float* h1 = &smem[E_H1 + tl * 65 + o4];
            h1[0] = gelu_exact(acc.x);
            h1[1] = gelu_exact(acc.y);
            h1[2] = gelu_exact(acc.z);
            h1[3] = gelu_exact(acc.w);
        }
        __syncthreads();

        // gx GEMM (FFMA2): gx[64][384] = h1 @ w_ih^T + b_ih -> global
        for (int task = tid; task < 64 * 48; task += 512) {
            int tl = task & 63;
            int h8 = (task >> 6) << 3;
            u64 a0 = *(const u64*)&smem[E_BIH + h8];
            u64 a1 = *(const u64*)&smem[E_BIH + h8 + 2];
            u64 a2 = *(const u64*)&smem[E_BIH + h8 + 4];
            u64 a3 = *(const u64*)&smem[E_BIH + h8 + 6];
            const float* h1p = &smem[E_H1 + tl * 65];
            #pragma unroll 16
            for (int d = 0; d < 64; d++) {
                float hv = h1p[d];
                u64 h2 = pk2(hv, hv);
                const u64* w = (const u64*)&smem[E_WIH + d * 384 + h8];
                a0 = fma2(h2, w[0], a0);
                a1 = fma2(h2, w[1], a1);
                a2 = fma2(h2, w[2], a2);
                a3 = fma2(h2, w[3], a3);
            }
            float2 r0 = upk2(a0), r1 = upk2(a1), r2 = upk2(a2), r3 = upk2(a3);
            float* gp = g_gx_buf + ((size_t)b * TT + t0 + tl) * G3 + h8;
            *(float4*)gp       = make_float4(r0.x, r0.y, r1.x, r1.y);
            *(float4*)(gp + 4) = make_float4(r2.x, r2.y, r3.x, r3.y);
        }
        __syncthreads();
    }
}

// ---------------- K3: GRU recurrence, 1 CTA per batch, w_hh register-resident ----------------
__global__ __launch_bounds__(384, 1) void k_gru(const float* __restrict__ whh,
                                                const float* __restrict__ bhh) {
    __shared__ __align__(16) float sh[DGG];   // hidden state
    __shared__ float sA[G3];                  // gh (+gx for r,z chunks)
    __shared__ float sGn[DGG];                // gx_n
    int b = blockIdx.x;
    int j = threadIdx.x;

    // register-resident row of w_hh: 64 f32x2 pairs
    u64 w[64];
    {
        const u64* wp = (const u64*)(whh + (size_t)j * DGG);
        #pragma unroll
        for (int i = 0; i < 64; i++) w[i] = wp[i];
    }
    float bj = bhh[j];
    if (j < DGG) sh[j] = 0.f;

    size_t base = (size_t)b * TT * G3 + j;
    float nxt = g_gx_buf[base];

    for (int t = 0; t < TT; t++) {
        __syncthreads();                      // h ready
        float gx = nxt;
        if (t < TT - 1) nxt = g_gx_buf[base + (size_t)(t + 1) * G3];  // prefetch
        u64 acc0 = pk2(bj, 0.f);
        u64 acc1 = pk2(0.f, 0.f);
        const ulonglong2* hp = (const ulonglong2*)sh;
        #pragma unroll
        for (int i = 0; i < 32; i++) {
            ulonglong2 hv = hp[i];            // broadcast LDS.128
            acc0 = fma2(hv.x, w[2 * i], acc0);
            acc1 = fma2(hv.y, w[2 * i + 1], acc1);
        }
        float2 s0 = upk2(acc0), s1 = upk2(acc1);
        float gh = (s0.x + s0.y) + (s1.x + s1.y);
        if (j < 256) {
            sA[j] = gh + gx;
        } else {
            sA[j] = gh;
            sGn[j - 256] = gx;
        }
        __syncthreads();
        if (j < DGG) {
            float r = sigm(sA[j]);
            float z = sigm(sA[j + 128]);
            float n = tanh_fast(sGn[j] + r * sA[j + 256]);
            float h = sh[j];
            float hn = (1.f - z) * n + z * h;
            sh[j] = hn;
            g_z_buf[((size_t)b * TT + t) * DGG + j] = hn;
        }
    }
}

// ---------------- K4: recon head (FFMA2, token-pair packed) + masked normalized loss ----------------
#define H_W1   0        // 128x128 [k][o]
#define H_W2   16384    // 128x128
#define H_W3   32768    // 128x64
#define H_B1   40960    // 128
#define H_B2   41088    // 128
#define H_B3   41216    // 64
#define H_INV  41280    // 64
#define H_ZB   41344    // 128x34 (pad)
#define H_RB   45696    // 128x34
#define H_TOT  50048    // floats -> 200192 bytes

__global__ __launch_bounds__(256, 1) void k_head(
    const float* __restrict__ x,
    const float* __restrict__ h1_w, const float* __restrict__ h1_b,
    const float* __restrict__ h2_w, const float* __restrict__ h2_b,
    const float* __restrict__ h3_w, const float* __restrict__ h3_b)
{
    extern __shared__ float smem[];
    __shared__ double sred[256];
    int tid = threadIdx.x;

    for (int i = tid; i < 16384; i += 256) smem[H_W1 + i] = h1_w[i];
    for (int i = tid; i < 16384; i += 256) smem[H_W2 + i] = h2_w[i];
    for (int i = tid; i < 8192; i += 256) smem[H_W3 + i] = h3_w[i];
    for (int i = tid; i < 128; i += 256) { smem[H_B1 + i] = h1_b[i]; smem[H_B2 + i] = h2_b[i]; }
    for (int i = tid; i < 64; i += 256) smem[H_B3 + i] = h3_b[i];
    if (tid < 64) {
        double N = (double)(BB * TT);
        double mean = g_sum[tid] / N;
        double var = (g_sumsq[tid] - N * mean * mean) / (N - 1.0);
        double sd = sqrt(var) + 1e-8;
        smem[H_INV + tid] = (float)(1.0 / (sd * sd));
    }
    __syncthreads();

    float lacc = 0.f;

    for (int tile = blockIdx.x; tile < BB * (TT / 32); tile += gridDim.x) {
        int b = tile >> 7;
        int t0 = (tile & 127) << 5;
        __syncthreads();  // previous tile's readers done before ZB rewrite

        // load z transposed [k][t]
        for (int i = tid; i < 4096; i += 256) {
            int k = i & 127, t = i >> 7;
            smem[H_ZB + k * 34 + t] = g_z_buf[((size_t)b * TT + t0 + t) * DGG + k];
        }
        __syncthreads();

        // layer1: ZB -> RB  (o = tid&127, g = tid>>7 handles 8 token-pairs)
        {
            int o = tid & 127, g = tid >> 7;
            float bo = smem[H_B1 + o];
            u64 A[8];
            #pragma unroll
            for (int p = 0; p < 8; p++) A[p] = pk2(bo, bo);
            #pragma unroll 4
            for (int k = 0; k < 128; k++) {
                float wv = smem[H_W1 + k * 128 + o];
                u64 w2 = pk2(wv, wv);
                const float* zr = &smem[H_ZB + k * 34 + g * 16];
                #pragma unroll
                for (int p = 0; p < 8; p++) A[p] = fma2(*(const u64*)(zr + 2 * p), w2, A[p]);
            }
            float* rr = &smem[H_RB + o * 34 + g * 16];
            #pragma unroll
            for (int p = 0; p < 8; p++) {
                float2 v = upk2(A[p]);
                rr[2 * p]     = gelu_exact(v.x);
                rr[2 * p + 1] = gelu_exact(v.y);
            }
        }
        __syncthreads();

        // layer2: RB -> ZB
        {
            int o = tid & 127, g = tid >> 7;
            float bo = smem[H_B2 + o];
            u64 A[8];
            #pragma unroll
            for (int p = 0; p < 8; p++) A[p] = pk2(bo, bo);
            #pragma unroll 4
            for (int k = 0; k < 128; k++) {
                float wv = smem[H_W2 + k * 128 + o];
                u64 w2 = pk2(wv, wv);
                const float* zr = &smem[H_RB + k * 34 + g * 16];
                #pragma unroll
                for (int p = 0; p < 8; p++) A[p] = fma2(*(const u64*)(zr + 2 * p), w2, A[p]);
            }
            float* rr = &smem[H_ZB + o * 34 + g * 16];
            #pragma unroll
            for (int p = 0; p < 8; p++) {
                float2 v = upk2(A[p]);
                rr[2 * p]     = gelu_exact(v.x);
                rr[2 * p + 1] = gelu_exact(v.y);
            }
        }
        __syncthreads();

        // layer3 + loss: o = tid&63, g = tid>>6 handles 4 token-pairs
        {
            int o = tid & 63, g = tid >> 6;
            float bo = smem[H_B3 + o];
            float invs = smem[H_INV + o];
            u64 A[4];
            #pragma unroll
            for (int p = 0; p < 4; p++) A[p] = pk2(bo, bo);
            #pragma unroll 4
            for (int k = 0; k < 128; k++) {
                float wv = smem[H_W3 + k * 64 + o];
                u64 w2 = pk2(wv, wv);
                const float* zr = &smem[H_ZB + k * 34 + g * 8];
                #pragma unroll
                for (int p = 0; p < 4; p++) A[p] = fma2(*(const u64*)(zr + 2 * p), w2, A[p]);
            }
            #pragma unroll
            for (int p = 0; p < 4; p++) {
                int t = t0 + g * 8 + 2 * p;
                size_t gi = ((size_t)b * TT + t) * FF + o;
                float2 v = upk2(A[p]);
                float d0 = v.x - x[gi];
                float d1 = v.y - x[gi + FF];
                if (g_mask[gi])      lacc = fmaf(d0 * d0, invs, lacc);
                if (g_mask[gi + FF]) lacc = fmaf(d1 * d1, invs, lacc);
            }
        }
    }

    sred[tid] = (double)lacc;
    __syncthreads();
    for (int s = 128; s > 0; s >>= 1) {
        if (tid < s) sred[tid] += sred[tid + s];
        __syncthreads();
    }
    if (tid == 0) atomicAdd(&g_loss, sred[0]);
}

// ---------------- K5: finalize ----------------
__global__ void k_final(float* out) {
    double denom = g_mcnt > 1.0 ? g_mcnt : 1.0;
    out[0] = (float)(g_loss / denom);
}

// ---------------- launch ----------------
extern "C" void kernel_launch(void* const* d_in, const int* in_sizes, int n_in,
                              void* d_out, int out_size) {
    const float* x          = (const float*)d_in[0];
    const void*  fm         = (const void*)d_in[1];
    const float* stem_w     = (const float*)d_in[2];
    const float* stem_b     = (const float*)d_in[3];
    const float* conv_w     = (const float*)d_in[4];
    const float* conv_b     = (const float*)d_in[5];
    const float* gru_w_ih   = (const float*)d_in[6];
    const float* gru_w_hh   = (const float*)d_in[7];
    const float* gru_b_ih   = (const float*)d_in[8];
    const float* gru_b_hh   = (const float*)d_in[9];
    const float* h1_w       = (const float*)d_in[10];
    const float* h1_b       = (const float*)d_in[11];
    const float* h2_w       = (const float*)d_in[12];
    const float* h2_b       = (const float*)d_in[13];
    const float* h3_w       = (const float*)d_in[14];
    const float* h3_b       = (const float*)d_in[15];
    float* out = (float*)d_out;

    cudaFuncSetAttribute(k_encoder, cudaFuncAttributeMaxDynamicSharedMemorySize, E_TOT * 4);
    cudaFuncSetAttribute(k_head, cudaFuncAttributeMaxDynamicSharedMemorySize, H_TOT * 4);

    k_init<<<1, 128>>>();
    k_probe<<<256, 256>>>((const unsigned int*)fm);
    k_mkconv<<<512, 256>>>(fm);
    k_stats<<<512, 256>>>(x);
    k_encoder<<<148, 512, E_TOT * 4>>>(x, stem_w, stem_b, conv_w, conv_b, gru_w_ih, gru_b_ih);
    k_gru<<<BB, 384>>>(gru_w_hh, gru_b_hh);
    k_head<<<148, 256, H_TOT * 4>>>(x, h1_w, h1_b, h2_w, h2_b, h3_w, h3_b);
    k_final<<<1, 1>>>(out);
}

// round 3
// speedup vs baseline: 1.1219x; 1.1219x over previous
#include <cuda_runtime.h>
#include <cuda_bf16.h>
#include <math.h>

#define BB 64
#define TT 4096
#define FF 64
#define DHH 64
#define DGG 128
#define G3 384   // 3*DG
#define HEADCTAS 84

typedef unsigned long long u64;

// ---------------- scratch (device globals; no cudaMalloc allowed) ----------------
// gx stored TRANSPOSED: [b][h][t]  (h in 0..383)
__device__ __align__(128) float g_gx_buf[(size_t)BB * G3 * TT];   // 402.7 MB
__device__ __align__(128) float g_z_buf[(size_t)BB * TT * DGG];   // 134.2 MB
__device__ __align__(128) unsigned char g_mask[(size_t)BB * TT * FF]; // 16.7 MB
__device__ double g_sum[FF];
__device__ double g_sumsq[FF];
__device__ double g_mcnt;
__device__ double g_loss;
__device__ int g_flag_byte;
__device__ int g_flag_half;
__device__ int g_prog[BB];    // GRU progress per batch (t rows published)

// ---------------- helpers ----------------
__device__ __forceinline__ u64 pk2(float lo, float hi) {
    u64 r; asm("mov.b64 %0, {%1, %2};" : "=l"(r) : "f"(lo), "f"(hi)); return r;
}
__device__ __forceinline__ float2 upk2(u64 v) {
    float2 r; asm("mov.b64 {%0, %1}, %2;" : "=f"(r.x), "=f"(r.y) : "l"(v)); return r;
}
__device__ __forceinline__ u64 fma2(u64 a, u64 b, u64 c) {
    u64 d; asm("fma.rn.f32x2 %0, %1, %2, %3;" : "=l"(d) : "l"(a), "l"(b), "l"(c)); return d;
}
__device__ __forceinline__ float gelu_exact(float a) {
    return 0.5f * a * (1.0f + erff(a * 0.70710678118654752440f));
}
__device__ __forceinline__ float sigm(float x) {
    return __fdividef(1.0f, 1.0f + __expf(-x));
}
__device__ __forceinline__ float tanh_fast(float x) {
    float s = copysignf(1.0f, x);
    float e = __expf(-2.0f * fabsf(x));
    return s * __fdividef(1.0f - e, 1.0f + e);
}

// ---------------- K0: reset accumulators (graph replays!) ----------------
__global__ void k_init() {
    int t = threadIdx.x;
    if (t < FF) { g_sum[t] = 0.0; g_sumsq[t] = 0.0; g_prog[t] = 0; }
    if (t == FF) g_mcnt = 0.0;
    if (t == FF + 1) g_loss = 0.0;
    if (t == FF + 2) g_flag_byte = 0;
    if (t == FF + 3) g_flag_half = 0;
}

// ---------------- K0b: probe mask element width from bit patterns ----------------
__global__ __launch_bounds__(256) void k_probe(const unsigned int* __restrict__ m) {
    int byteF = 0, halfF = 0;
    size_t nwords = (size_t)BB * TT * FF / 4;
    for (size_t i = (size_t)blockIdx.x * blockDim.x + threadIdx.x; i < nwords;
         i += (size_t)gridDim.x * blockDim.x) {
        unsigned v = m[i];
        if (v == 0u || v == 1u || v == 0x3F800000u) continue;
        bool b01 = true;
        #pragma unroll
        for (int k = 0; k < 4; k++) {
            unsigned bt = (v >> (8 * k)) & 0xFFu;
            if (bt > 1u) b01 = false;
        }
        if (b01) { byteF = 1; continue; }
        bool h16 = true;
        #pragma unroll
        for (int k = 0; k < 2; k++) {
            unsigned h = (v >> (16 * k)) & 0xFFFFu;
            if (h != 0u && h != 0x3F80u) h16 = false;
        }
        if (h16) { halfF = 1; continue; }
        byteF = 1;
    }
    if (byteF) g_flag_byte = 1;
    if (halfF) g_flag_half = 1;
}

// ---------------- K0c: canonicalize mask to uint8 ----------------
__global__ __launch_bounds__(256) void k_mkconv(const void* __restrict__ m) {
    int bF = g_flag_byte, hF = g_flag_half;
    size_t N = (size_t)BB * TT * FF;
    for (size_t i = (size_t)blockIdx.x * blockDim.x + threadIdx.x; i < N;
         i += (size_t)gridDim.x * blockDim.x) {
        unsigned char r;
        if (bF)      r = (((const unsigned char*)m)[i] != 0);
        else if (hF) r = (((const unsigned short*)m)[i] != 0);
        else         r = (((const unsigned int*)m)[i] != 0);
        g_mask[i] = r;
    }
}

// ---------------- K1: per-feature sum/sumsq + mask count (vectorized) ----------------
__global__ __launch_bounds__(256) void k_stats(const float* __restrict__ x) {
    int tid = threadIdx.x;
    int f4 = (tid & 15) * 4;      // feature group base
    int rg = tid >> 4;            // 0..15 row groups
    float4 s = make_float4(0.f, 0.f, 0.f, 0.f);
    float4 q = make_float4(0.f, 0.f, 0.f, 0.f);
    int mc = 0;
    for (int r = blockIdx.x * 16 + rg; r < BB * TT; r += gridDim.x * 16) {
        size_t gi = (size_t)r * FF + f4;
        float4 v = *(const float4*)(x + gi);
        unsigned mw = *(const unsigned*)(g_mask + gi);
        s.x += v.x; s.y += v.y; s.z += v.z; s.w += v.w;
        q.x = fmaf(v.x, v.x, q.x); q.y = fmaf(v.y, v.y, q.y);
        q.z = fmaf(v.z, v.z, q.z); q.w = fmaf(v.w, v.w, q.w);
        mc += __popc(mw & 0x01010101u);
    }
    __shared__ float ss[16][64]; __shared__ float sq[16][64]; __shared__ int sm_[256];
    ss[rg][f4] = s.x; ss[rg][f4 + 1] = s.y; ss[rg][f4 + 2] = s.z; ss[rg][f4 + 3] = s.w;
    sq[rg][f4] = q.x; sq[rg][f4 + 1] = q.y; sq[rg][f4 + 2] = q.z; sq[rg][f4 + 3] = q.w;
    sm_[tid] = mc;
    __syncthreads();
    if (tid < 64) {
        double S = 0.0, Q = 0.0;
        #pragma unroll
        for (int g = 0; g < 16; g++) { S += (double)ss[g][tid]; Q += (double)sq[g][tid]; }
        atomicAdd(&g_sum[tid], S);
        atomicAdd(&g_sumsq[tid], Q);
    }
    if (tid < 128) sm_[tid] += sm_[tid + 128];
    __syncthreads();
    if (tid < 64) sm_[tid] += sm_[tid + 64];
    __syncthreads();
    if (tid == 0) {
        int tot = 0;
        for (int i = 0; i < 64; i++) tot += sm_[i];
        atomicAdd(&g_mcnt, (double)tot);
    }
}

// ---------------- K2: fused mask+stem+GELU+conv+GELU+gx GEMM (FFMA2) ----------------
#define E_W1   0        // 64x64  stem_w [f][d]
#define E_CW   4096     // 192x64 conv_w transposed [(i*3+k)][o]
#define E_WIH  16384    // 64x384 w_ih transposed [d][h]
#define E_SB   40960
#define E_CB   41024
#define E_BIH  41088
#define E_X    41472    // 66x64
#define E_H0   45696    // 66x64
#define E_H1   49920    // 64x65
#define E_TOT  54080    // floats -> 216320 bytes

__global__ __launch_bounds__(1024, 1) void k_encoder(
    const float* __restrict__ x,
    const float* __restrict__ stem_w, const float* __restrict__ stem_b,
    const float* __restrict__ conv_w, const float* __restrict__ conv_b,
    const float* __restrict__ w_ih, const float* __restrict__ b_ih)
{
    extern __shared__ float smem[];
    int tid = threadIdx.x;
    const int NT = 1024;

    for (int i = tid; i < 4096; i += NT) smem[E_W1 + i] = stem_w[i];
    for (int i = tid; i < 12288; i += NT) {
        int o = i & 63, ik = i >> 6;
        smem[E_CW + i] = conv_w[o * 192 + ik];
    }
    for (int i = tid; i < 24576; i += NT) {
        int h = i % 384, d = i / 384;
        smem[E_WIH + i] = w_ih[h * 64 + d];
    }
    if (tid < 64) { smem[E_SB + tid] = stem_b[tid]; smem[E_CB + tid] = conv_b[tid]; }
    if (tid >= 64 && tid < 448) smem[E_BIH + tid - 64] = b_ih[tid - 64];
    __syncthreads();

    for (int tile = blockIdx.x; tile < BB * (TT / 64); tile += gridDim.x) {
        int b = tile >> 6;
        int t0 = (tile & 63) << 6;

        for (int i = tid; i < 66 * 64; i += NT) {
            int row = i >> 6, f = i & 63;
            int t = t0 - 1 + row;
            float v = 0.f;
            if (t >= 0 && t < TT) {
                size_t gi = ((size_t)b * TT + t) * FF + f;
                v = g_mask[gi] ? 0.f : x[gi];
            }
            smem[E_X + i] = v;
        }
        __syncthreads();

        // stem GEMM + GELU (FFMA2)
        for (int q = tid; q < 66 * 16; q += NT) {
            int i = q >> 4, d4 = (q & 15) << 2;
            int t = t0 - 1 + i;
            const u64* bp = (const u64*)&smem[E_SB + d4];
            u64 a0 = bp[0], a1 = bp[1];
            const float* xr = &smem[E_X + i * 64];
            #pragma unroll 16
            for (int f = 0; f < 64; f++) {
                float xv = xr[f];
                u64 x2 = pk2(xv, xv);
                const u64* w = (const u64*)&smem[E_W1 + f * 64 + d4];
                a0 = fma2(x2, w[0], a0);
                a1 = fma2(x2, w[1], a1);
            }
            bool valid = (t >= 0) && (t < TT);
            float2 v0 = upk2(a0), v1 = upk2(a1);
            float4 r;
            r.x = valid ? gelu_exact(v0.x) : 0.f;
            r.y = valid ? gelu_exact(v0.y) : 0.f;
            r.z = valid ? gelu_exact(v1.x) : 0.f;
            r.w = valid ? gelu_exact(v1.y) : 0.f;
            *(float4*)&smem[E_H0 + i * 64 + d4] = r;
        }
        __syncthreads();

        // conv1d k=3 + GELU (FFMA2)
        for (int q = tid; q < 64 * 16; q += NT) {
            int tl = q >> 4, o4 = (q & 15) << 2;
            const u64* bp = (const u64*)&smem[E_CB + o4];
            u64 a0 = bp[0], a1 = bp[1];
            const float* h0a = &smem[E_H0 + tl * 64];
            const float* h0b = h0a + 64;
            const float* h0c = h0a + 128;
            #pragma unroll 8
            for (int i = 0; i < 64; i++) {
                u64 p0 = pk2(h0a[i], h0a[i]);
                u64 p1 = pk2(h0b[i], h0b[i]);
                u64 p2 = pk2(h0c[i], h0c[i]);
                const u64* w0 = (const u64*)&smem[E_CW + (i * 3 + 0) * 64 + o4];
                const u64* w1 = (const u64*)&smem[E_CW + (i * 3 + 1) * 64 + o4];
                const u64* w2 = (const u64*)&smem[E_CW + (i * 3 + 2) * 64 + o4];
                a0 = fma2(p0, w0[0], fma2(p1, w1[0], fma2(p2, w2[0], a0)));
                a1 = fma2(p0, w0[1], fma2(p1, w1[1], fma2(p2, w2[1], a1)));
            }
            float2 v0 = upk2(a0), v1 = upk2(a1);
            float* h1 = &smem[E_H1 + tl * 65 + o4];
            h1[0] = gelu_exact(v0.x);
            h1[1] = gelu_exact(v0.y);
            h1[2] = gelu_exact(v1.x);
            h1[3] = gelu_exact(v1.y);
        }
        __syncthreads();

        // gx GEMM -> TRANSPOSED store [b][h][t]
        for (int task = tid; task < 64 * 48; task += NT) {
            int tl = task & 63;
            int h8 = (task >> 6) << 3;
            u64 a0 = *(const u64*)&smem[E_BIH + h8];
            u64 a1 = *(const u64*)&smem[E_BIH + h8 + 2];
            u64 a2 = *(const u64*)&smem[E_BIH + h8 + 4];
            u64 a3 = *(const u64*)&smem[E_BIH + h8 + 6];
            const float* h1p = &smem[E_H1 + tl * 65];
            #pragma unroll 16
            for (int d = 0; d < 64; d++) {
                float hv = h1p[d];
                u64 h2 = pk2(hv, hv);
                const u64* w = (const u64*)&smem[E_WIH + d * 384 + h8];
                a0 = fma2(h2, w[0], a0);
                a1 = fma2(h2, w[1], a1);
                a2 = fma2(h2, w[2], a2);
                a3 = fma2(h2, w[3], a3);
            }
            float2 r0 = upk2(a0), r1 = upk2(a1), r2 = upk2(a2), r3 = upk2(a3);
            float* gp = g_gx_buf + ((size_t)b * G3 + h8) * TT + (t0 + tl);
            gp[0]          = r0.x;
            gp[(size_t)TT]     = r0.y;
            gp[(size_t)2 * TT] = r1.x;
            gp[(size_t)3 * TT] = r1.y;
            gp[(size_t)4 * TT] = r2.x;
            gp[(size_t)5 * TT] = r2.y;
            gp[(size_t)6 * TT] = r3.x;
            gp[(size_t)7 * TT] = r3.y;
        }
        __syncthreads();
    }
}

// ---------------- K3: fused GRU + head (overlapped via progress flags) ----------------
// grid = 64 (GRU role) + 84 (head role); 200KB smem/CTA -> 1 CTA/SM, all co-resident.

// head smem layout (floats, dynamic)
#define H_W1   0        // 128x128 [k][o]
#define H_W2   16384
#define H_W3   32768
#define H_B1   40960
#define H_B2   41088
#define H_B3   41216
#define H_INV  41280
#define H_ZB   41344    // 128x34
#define H_RB   45696    // 128x34
#define H_TOT  50048    // 200192 bytes

__device__ __forceinline__ void gru_step(
    int j, float gxv, const u64* __restrict__ w, float bj,
    float* sh, float* sA, float* sGn, float* zrow)
{
    __syncthreads();                      // h ready
    u64 acc0 = pk2(bj, 0.f);
    u64 acc1 = pk2(0.f, 0.f);
    const ulonglong2* hp = (const ulonglong2*)sh;
    #pragma unroll
    for (int i = 0; i < 32; i++) {
        ulonglong2 hv = hp[i];            // broadcast LDS.128
        acc0 = fma2(hv.x, w[2 * i], acc0);
        acc1 = fma2(hv.y, w[2 * i + 1], acc1);
    }
    float2 s0 = upk2(acc0), s1 = upk2(acc1);
    float gh = (s0.x + s0.y) + (s1.x + s1.y);
    if (j < 256) {
        sA[j] = gh + gxv;
    } else {
        sA[j] = gh;
        sGn[j - 256] = gxv;
    }
    __syncthreads();
    if (j < DGG) {
        float r = sigm(sA[j]);
        float z = sigm(sA[j + 128]);
        float n = tanh_fast(sGn[j] + r * sA[j + 256]);
        float h = sh[j];
        float hn = (1.f - z) * n + z * h;
        sh[j] = hn;
        zrow[j] = hn;
    }
}

__global__ __launch_bounds__(384, 1) void k_gruhead(
    const float* __restrict__ whh, const float* __restrict__ bhh,
    const float* __restrict__ x,
    const float* __restrict__ h1_w, const float* __restrict__ h1_b,
    const float* __restrict__ h2_w, const float* __restrict__ h2_b,
    const float* __restrict__ h3_w, const float* __restrict__ h3_b)
{
    extern __shared__ float smem[];

    if (blockIdx.x < BB) {
        // ================= GRU role =================
        float* sh  = smem;            // 128
        float* sA  = smem + 128;      // 384
        float* sGn = smem + 512;      // 128
        int b = blockIdx.x;
        int j = threadIdx.x;

        u64 w[64];
        {
            const u64* wp = (const u64*)(whh + (size_t)j * DGG);
            #pragma unroll
            for (int i = 0; i < 64; i++) w[i] = wp[i];
        }
        float bj = bhh[j];
        if (j < DGG) sh[j] = 0.f;

        const float4* gxp = (const float4*)(g_gx_buf + ((size_t)b * G3 + j) * TT);
        float* zbase = g_z_buf + (size_t)b * TT * DGG;
        float4 cur = gxp[0];
        float4 nxt = gxp[1];

        for (int tb = 0; tb < TT / 4; tb++) {
            float4 pf;
            bool havepf = (tb + 2 < TT / 4);
            if (havepf) pf = gxp[tb + 2];
            int t = tb * 4;

            // publish progress every 32 steps: rows [0, t) are globally visible
            if (j == 0 && (t & 31) == 0 && t > 0) {
                __threadfence();
                asm volatile("st.global.release.gpu.b32 [%0], %1;"
                             :: "l"(&g_prog[b]), "r"(t) : "memory");
            }

            gru_step(j, cur.x, w, bj, sh, sA, sGn, zbase + (size_t)(t + 0) * DGG);
            gru_step(j, cur.y, w, bj, sh, sA, sGn, zbase + (size_t)(t + 1) * DGG);
            gru_step(j, cur.z, w, bj, sh, sA, sGn, zbase + (size_t)(t + 2) * DGG);
            gru_step(j, cur.w, w, bj, sh, sA, sGn, zbase + (size_t)(t + 3) * DGG);

            cur = nxt;
            if (havepf) nxt = pf;
        }
        __syncthreads();
        if (j == 0) {
            __threadfence();
            asm volatile("st.global.release.gpu.b32 [%0], %1;"
                         :: "l"(&g_prog[b]), "r"(TT) : "memory");
        }
        return;
    }

    // ================= head role =================
    if (threadIdx.x >= 256) return;
    int tid = threadIdx.x;
    int hb = blockIdx.x - BB;          // 0..83
    __shared__ double sred[256];

    for (int i = tid; i < 16384; i += 256) smem[H_W1 + i] = h1_w[i];
    for (int i = tid; i < 16384; i += 256) smem[H_W2 + i] = h2_w[i];
    for (int i = tid; i < 8192; i += 256) smem[H_W3 + i] = h3_w[i];
    if (tid < 128) { smem[H_B1 + tid] = h1_b[tid]; smem[H_B2 + tid] = h2_b[tid]; }
    if (tid >= 128 && tid < 192) smem[H_B3 + tid - 128] = h3_b[tid - 128];
    if (tid < 64) {
        double N = (double)(BB * TT);
        double mean = g_sum[tid] / N;
        double var = (g_sumsq[tid] - N * mean * mean) / (N - 1.0);
        double sd = sqrt(var) + 1e-8;
        smem[H_INV + tid] = (float)(1.0 / (sd * sd));
    }
    __syncthreads();

    float lacc = 0.f;

    // t-major tile order so head streams right behind the GRU producers
    for (int tile = hb; tile < BB * (TT / 32); tile += HEADCTAS) {
        int b = tile & 63;
        int t0 = (tile >> 6) << 5;

        // wait until GRU b has published rows [0, t0+32)
        if (tid == 0) {
            long long t_start = clock64();
            while (true) {
                int p;
                asm volatile("ld.global.acquire.gpu.b32 %0, [%1];"
                             : "=r"(p) : "l"(&g_prog[b]) : "memory");
                if (p >= t0 + 32) break;
                if (clock64() - t_start > 4000000000LL) break;  // safety valve
            }
        }
        __syncthreads();   // also protects ZB from previous tile's readers

        for (int i = tid; i < 4096; i += 256) {
            int k = i & 127, t = i >> 7;
            smem[H_ZB + k * 34 + t] = g_z_buf[((size_t)b * TT + t0 + t) * DGG + k];
        }
        __syncthreads();

        // layer1
        {
            int o = tid & 127, g = tid >> 7;
            float bo = smem[H_B1 + o];
            u64 A[8];
            #pragma unroll
            for (int p = 0; p < 8; p++) A[p] = pk2(bo, bo);
            #pragma unroll 4
            for (int k = 0; k < 128; k++) {
                float wv = smem[H_W1 + k * 128 + o];
                u64 w2 = pk2(wv, wv);
                const float* zr = &smem[H_ZB + k * 34 + g * 16];
                #pragma unroll
                for (int p = 0; p < 8; p++) A[p] = fma2(*(const u64*)(zr + 2 * p), w2, A[p]);
            }
            float* rr = &smem[H_RB + o * 34 + g * 16];
            #pragma unroll
            for (int p = 0; p < 8; p++) {
                float2 v = upk2(A[p]);
                rr[2 * p]     = gelu_exact(v.x);
                rr[2 * p + 1] = gelu_exact(v.y);
            }
        }
        __syncthreads();

        // layer2
        {
            int o = tid & 127, g = tid >> 7;
            float bo = smem[H_B2 + o];
            u64 A[8];
            #pragma unroll
            for (int p = 0; p < 8; p++) A[p] = pk2(bo, bo);
            #pragma unroll 4
            for (int k = 0; k < 128; k++) {
                float wv = smem[H_W2 + k * 128 + o];
                u64 w2 = pk2(wv, wv);
                const float* zr = &smem[H_RB + k * 34 + g * 16];
                #pragma unroll
                for (int p = 0; p < 8; p++) A[p] = fma2(*(const u64*)(zr + 2 * p), w2, A[p]);
            }
            float* rr = &smem[H_ZB + o * 34 + g * 16];
            #pragma unroll
            for (int p = 0; p < 8; p++) {
                float2 v = upk2(A[p]);
                rr[2 * p]     = gelu_exact(v.x);
                rr[2 * p + 1] = gelu_exact(v.y);
            }
        }
        __syncthreads();

        // layer3 + loss
        {
            int o = tid & 63, g = tid >> 6;
            float bo = smem[H_B3 + o];
            float invs = smem[H_INV + o];
            u64 A[4];
            #pragma unroll
            for (int p = 0; p < 4; p++) A[p] = pk2(bo, bo);
            #pragma unroll 4
            for (int k = 0; k < 128; k++) {
                float wv = smem[H_W3 + k * 64 + o];
                u64 w2 = pk2(wv, wv);
                const float* zr = &smem[H_ZB + k * 34 + g * 8];
                #pragma unroll
                for (int p = 0; p < 4; p++) A[p] = fma2(*(const u64*)(zr + 2 * p), w2, A[p]);
            }
            #pragma unroll
            for (int p = 0; p < 4; p++) {
                int t = t0 + g * 8 + 2 * p;
                size_t gi = ((size_t)b * TT + t) * FF + o;
                float2 v = upk2(A[p]);
                float d0 = v.x - x[gi];
                float d1 = v.y - x[gi + FF];
                if (g_mask[gi])      lacc = fmaf(d0 * d0, invs, lacc);
                if (g_mask[gi + FF]) lacc = fmaf(d1 * d1, invs, lacc);
            }
        }
    }

    sred[tid] = (double)lacc;
    __syncthreads();
    for (int s = 128; s > 0; s >>= 1) {
        if (tid < s) sred[tid] += sred[tid + s];
        __syncthreads();
    }
    if (tid == 0) atomicAdd(&g_loss, sred[0]);
}

// ---------------- K5: finalize ----------------
__global__ void k_final(float* out) {
    double denom = g_mcnt > 1.0 ? g_mcnt : 1.0;
    out[0] = (float)(g_loss / denom);
}

// ---------------- launch ----------------
extern "C" void kernel_launch(void* const* d_in, const int* in_sizes, int n_in,
                              void* d_out, int out_size) {
    const float* x          = (const float*)d_in[0];
    const void*  fm         = (const void*)d_in[1];
    const float* stem_w     = (const float*)d_in[2];
    const float* stem_b     = (const float*)d_in[3];
    const float* conv_w     = (const float*)d_in[4];
    const float* conv_b     = (const float*)d_in[5];
    const float* gru_w_ih   = (const float*)d_in[6];
    const float* gru_w_hh   = (const float*)d_in[7];
    const float* gru_b_ih   = (const float*)d_in[8];
    const float* gru_b_hh   = (const float*)d_in[9];
    const float* h1_w       = (const float*)d_in[10];
    const float* h1_b       = (const float*)d_in[11];
    const float* h2_w       = (const float*)d_in[12];
    const float* h2_b       = (const float*)d_in[13];
    const float* h3_w       = (const float*)d_in[14];
    const float* h3_b       = (const float*)d_in[15];
    float* out = (float*)d_out;

    cudaFuncSetAttribute(k_encoder, cudaFuncAttributeMaxDynamicSharedMemorySize, E_TOT * 4);
    cudaFuncSetAttribute(k_gruhead, cudaFuncAttributeMaxDynamicSharedMemorySize, H_TOT * 4);

    k_init<<<1, 128>>>();
    k_probe<<<256, 256>>>((const unsigned int*)fm);
    k_mkconv<<<512, 256>>>(fm);
    k_stats<<<512, 256>>>(x);
    k_encoder<<<148, 1024, E_TOT * 4>>>(x, stem_w, stem_b, conv_w, conv_b, gru_w_ih, gru_b_ih);
    k_gruhead<<<BB + HEADCTAS, 384, H_TOT * 4>>>(gru_w_hh, gru_b_hh, x,
                                                 h1_w, h1_b, h2_w, h2_b, h3_w, h3_b);
    k_final<<<1, 1>>>(out);
}

// round 4
// speedup vs baseline: 1.2354x; 1.1012x over previous
#include <cuda_runtime.h>
#include <cuda_bf16.h>
#include <math.h>

#define BB 64
#define TT 4096
#define FF 64
#define DHH 64
#define DGG 128
#define G3 384   // 3*DG
#define WCTAS 84 // worker (encoder->head) CTAs

typedef unsigned long long u64;

// ---------------- scratch (device globals; no cudaMalloc allowed) ----------------
// gx stored TRANSPOSED: [b][h][t]
__device__ __align__(128) float g_gx_buf[(size_t)BB * G3 * TT];   // 402.7 MB
__device__ __align__(128) float g_z_buf[(size_t)BB * TT * DGG];   // 134.2 MB
__device__ __align__(128) unsigned char g_mask[(size_t)BB * TT * FF]; // 16.7 MB canonical
__device__ double g_sum[FF];
__device__ double g_sumsq[FF];
__device__ double g_mcnt;
__device__ double g_loss;
__device__ int g_flag_byte;
__device__ int g_flag_half;
__device__ int g_prog[BB];         // GRU progress per batch (t rows published)
__device__ int g_tiledone[64 * 64]; // encoder tile flags: [tb][b]
__device__ int g_statsctr;
__device__ int g_headctr;

// ---------------- helpers ----------------
__device__ __forceinline__ u64 pk2(float lo, float hi) {
    u64 r; asm("mov.b64 %0, {%1, %2};" : "=l"(r) : "f"(lo), "f"(hi)); return r;
}
__device__ __forceinline__ float2 upk2(u64 v) {
    float2 r; asm("mov.b64 {%0, %1}, %2;" : "=f"(r.x), "=f"(r.y) : "l"(v)); return r;
}
__device__ __forceinline__ u64 fma2(u64 a, u64 b, u64 c) {
    u64 d; asm("fma.rn.f32x2 %0, %1, %2, %3;" : "=l"(d) : "l"(a), "l"(b), "l"(c)); return d;
}
__device__ __forceinline__ float gelu_exact(float a) {
    return 0.5f * a * (1.0f + erff(a * 0.70710678118654752440f));
}
__device__ __forceinline__ float sigm(float x) {
    return __fdividef(1.0f, 1.0f + __expf(-x));
}
__device__ __forceinline__ float tanh_fast(float x) {
    float s = copysignf(1.0f, x);
    float e = __expf(-2.0f * fabsf(x));
    return s * __fdividef(1.0f - e, 1.0f + e);
}
__device__ __forceinline__ int ld_acq(const int* p) {
    int v; asm volatile("ld.global.acquire.gpu.b32 %0, [%1];" : "=r"(v) : "l"(p) : "memory");
    return v;
}
__device__ __forceinline__ void st_rel(int* p, int v) {
    asm volatile("st.global.release.gpu.b32 [%0], %1;" :: "l"(p), "r"(v) : "memory");
}
__device__ __forceinline__ void spin_ge(const int* p, int target) {
    long long t0 = clock64();
    while (ld_acq(p) < target) {
        if (clock64() - t0 > 20000000000LL) break;  // safety valve
    }
}

// ---------------- K0a: reset scalars ----------------
__global__ void k_init() {
    int t = threadIdx.x;
    if (t < FF) { g_sum[t] = 0.0; g_sumsq[t] = 0.0; }
    if (t == FF)     g_mcnt = 0.0;
    if (t == FF + 1) g_loss = 0.0;
    if (t == FF + 2) g_flag_byte = 0;
    if (t == FF + 3) g_flag_half = 0;
    if (t == FF + 4) g_statsctr = 0;
    if (t == FF + 5) g_headctr = 0;
}

// ---------------- K0b: reset flag arrays ----------------
__global__ void k_init2() {
    int i = blockIdx.x * blockDim.x + threadIdx.x;
    if (i < 64 * 64) g_tiledone[i] = 0;
    if (i < BB) g_prog[i] = 0;
}

// ---------------- K1: probe mask element width from bit patterns ----------------
__global__ __launch_bounds__(256) void k_probe(const unsigned int* __restrict__ m) {
    int byteF = 0, halfF = 0;
    size_t nwords = (size_t)BB * TT * FF / 4;
    for (size_t i = (size_t)blockIdx.x * blockDim.x + threadIdx.x; i < nwords;
         i += (size_t)gridDim.x * blockDim.x) {
        unsigned v = m[i];
        if (v == 0u || v == 1u || v == 0x3F800000u) continue;
        bool b01 = true;
        #pragma unroll
        for (int k = 0; k < 4; k++) {
            unsigned bt = (v >> (8 * k)) & 0xFFu;
            if (bt > 1u) b01 = false;
        }
        if (b01) { byteF = 1; continue; }
        bool h16 = true;
        #pragma unroll
        for (int k = 0; k < 2; k++) {
            unsigned h = (v >> (16 * k)) & 0xFFFFu;
            if (h != 0u && h != 0x3F80u) h16 = false;
        }
        if (h16) { halfF = 1; continue; }
        byteF = 1;
    }
    if (byteF) g_flag_byte = 1;
    if (halfF) g_flag_half = 1;
}

// ---------------- encoder smem layout (floats) ----------------
#define E_W1   0        // 64x64  stem_w [f][d]
#define E_CW   4096     // 192x64 conv_w transposed [(i*3+k)][o]
#define E_WIH  16384    // 64x384 w_ih transposed [d][h]
#define E_SB   40960
#define E_CB   41024
#define E_BIH  41088
#define E_X    41472    // 66x64
#define E_H0   45696    // 66x64
#define E_H1   49920    // 64x65
#define E_TOT  54080    // floats -> 216320 bytes

// ---------------- head smem layout (floats) ----------------
#define H_W1   0        // 128x128 [k][o]
#define H_W2   16384
#define H_W3   32768
#define H_B1   40960
#define H_B2   41088
#define H_B3   41216
#define H_INV  41280
#define H_ZB   41344    // 128x34
#define H_RB   45696    // 128x34
#define H_TOT  50048    // floats; sred (256 dbl) + tile slot follow

#define SMEM_BYTES (E_TOT * 4)

// ---------------- GRU step ----------------
__device__ __forceinline__ void gru_step(
    int j, float gxv, const u64* __restrict__ w, float bj,
    float* sh, float* sA, float* sGn, float* zrow)
{
    __syncthreads();                      // h ready
    u64 acc0 = pk2(bj, 0.f);
    u64 acc1 = pk2(0.f, 0.f);
    const ulonglong2* hp = (const ulonglong2*)sh;
    #pragma unroll
    for (int i = 0; i < 32; i++) {
        ulonglong2 hv = hp[i];            // broadcast LDS.128
        acc0 = fma2(hv.x, w[2 * i], acc0);
        acc1 = fma2(hv.y, w[2 * i + 1], acc1);
    }
    float2 s0 = upk2(acc0), s1 = upk2(acc1);
    float gh = (s0.x + s0.y) + (s1.x + s1.y);
    if (j < 256) {
        sA[j] = gh + gxv;
    } else {
        sA[j] = gh;
        sGn[j - 256] = gxv;
    }
    __syncthreads();
    if (j < DGG) {
        float r = sigm(sA[j]);
        float z = sigm(sA[j + 128]);
        float n = tanh_fast(sGn[j] + r * sA[j + 256]);
        float h = sh[j];
        float hn = (1.f - z) * n + z * h;
        sh[j] = hn;
        zrow[j] = hn;
    }
}

// ---------------- K2: ONE persistent kernel: stats + encoder + GRU + head ----------------
__global__ __launch_bounds__(384, 1) void k_gruhead(
    const float* __restrict__ x, const void* __restrict__ fm,
    const float* __restrict__ stem_w, const float* __restrict__ stem_b,
    const float* __restrict__ conv_w, const float* __restrict__ conv_b,
    const float* __restrict__ w_ih, const float* __restrict__ b_ih,
    const float* __restrict__ whh, const float* __restrict__ bhh,
    const float* __restrict__ h1_w, const float* __restrict__ h1_b,
    const float* __restrict__ h2_w, const float* __restrict__ h2_b,
    const float* __restrict__ h3_w, const float* __restrict__ h3_b)
{
    extern __shared__ float smem[];
    int tid = threadIdx.x;
    const unsigned char* m8  = (const unsigned char*)fm;
    const unsigned short* m16 = (const unsigned short*)fm;
    const unsigned int* m32  = (const unsigned int*)fm;
    int bF = g_flag_byte, hF = g_flag_half;

    if (blockIdx.x < BB) {
        // ======================= GRU role (CTA b) =======================
        int b = blockIdx.x;

        // ---- stats partial on slice b (overlaps encoder ramp) ----
        {
            int f4 = (tid & 15) * 4;
            int rg = tid >> 4;      // 0..23
            float4 s = make_float4(0.f, 0.f, 0.f, 0.f);
            float4 q = make_float4(0.f, 0.f, 0.f, 0.f);
            int mc = 0;
            for (int r = b * 4096 + rg; r < (b + 1) * 4096; r += 24) {
                size_t gi = (size_t)r * FF + f4;
                float4 v = *(const float4*)(x + gi);
                int m0, m1, m2, m3;
                if (bF) {
                    unsigned w_ = *(const unsigned*)(m8 + gi);
                    m0 = (w_ & 0xFFu) != 0; m1 = ((w_ >> 8) & 0xFFu) != 0;
                    m2 = ((w_ >> 16) & 0xFFu) != 0; m3 = (w_ >> 24) != 0;
                } else if (hF) {
                    uint2 w_ = *(const uint2*)(m16 + gi);
                    m0 = (w_.x & 0xFFFFu) != 0; m1 = (w_.x >> 16) != 0;
                    m2 = (w_.y & 0xFFFFu) != 0; m3 = (w_.y >> 16) != 0;
                } else {
                    uint4 w_ = *(const uint4*)(m32 + gi);
                    m0 = w_.x != 0; m1 = w_.y != 0; m2 = w_.z != 0; m3 = w_.w != 0;
                }
                s.x += v.x; s.y += v.y; s.z += v.z; s.w += v.w;
                q.x = fmaf(v.x, v.x, q.x); q.y = fmaf(v.y, v.y, q.y);
                q.z = fmaf(v.z, v.z, q.z); q.w = fmaf(v.w, v.w, q.w);
                mc += m0 + m1 + m2 + m3;
            }
            float* ss = smem;            // 24x64
            float* sq = smem + 1536;     // 24x64
            int* sm_ = (int*)(smem + 3072);
            ss[rg * 64 + f4] = s.x; ss[rg * 64 + f4 + 1] = s.y;
            ss[rg * 64 + f4 + 2] = s.z; ss[rg * 64 + f4 + 3] = s.w;
            sq[rg * 64 + f4] = q.x; sq[rg * 64 + f4 + 1] = q.y;
            sq[rg * 64 + f4 + 2] = q.z; sq[rg * 64 + f4 + 3] = q.w;
            sm_[tid] = mc;
            __syncthreads();
            if (tid < 64) {
                double S = 0.0, Q = 0.0;
                #pragma unroll
                for (int g = 0; g < 24; g++) { S += (double)ss[g * 64 + tid]; Q += (double)sq[g * 64 + tid]; }
                atomicAdd(&g_sum[tid], S);
                atomicAdd(&g_sumsq[tid], Q);
            }
            __syncthreads();
            if (tid == 0) {
                int tot = 0;
                for (int i = 0; i < 384; i++) tot += sm_[i];
                atomicAdd(&g_mcnt, (double)tot);
                __threadfence();
                atomicAdd(&g_statsctr, 1);
            }
            __syncthreads();   // smem free for GRU reuse
        }

        // ---- GRU recurrence ----
        float* sh  = smem;            // 128
        float* sA  = smem + 128;      // 384
        float* sGn = smem + 512;      // 128
        int j = tid;

        u64 w[64];
        {
            const u64* wp = (const u64*)(whh + (size_t)j * DGG);
            #pragma unroll
            for (int i = 0; i < 64; i++) w[i] = wp[i];
        }
        float bj = bhh[j];
        if (j < DGG) sh[j] = 0.f;

        const float4* gxp = (const float4*)(g_gx_buf + ((size_t)b * G3 + j) * TT);
        float* zbase = g_z_buf + (size_t)b * TT * DGG;

        if (j == 0) spin_ge(&g_tiledone[0 * 64 + b], 1);   // region 0 ready
        __syncthreads();

        float4 cur = gxp[0];
        float4 nxt = gxp[1];

        for (int tb = 0; tb < TT / 4; tb++) {
            if ((tb & 15) == 0 && j == 0) {
                int reg = tb >> 4;
                if (reg + 1 < 64) spin_ge(&g_tiledone[(reg + 1) * 64 + b], 1); // lookahead
            }
            if (j == 0 && (tb & 7) == 0 && tb > 0) {
                __threadfence();
                st_rel(&g_prog[b], tb * 4);
            }
            float4 pf;
            bool havepf = (tb + 2 < TT / 4);
            if (havepf) pf = gxp[tb + 2];
            int t = tb * 4;

            gru_step(j, cur.x, w, bj, sh, sA, sGn, zbase + (size_t)(t + 0) * DGG);
            gru_step(j, cur.y, w, bj, sh, sA, sGn, zbase + (size_t)(t + 1) * DGG);
            gru_step(j, cur.z, w, bj, sh, sA, sGn, zbase + (size_t)(t + 2) * DGG);
            gru_step(j, cur.w, w, bj, sh, sA, sGn, zbase + (size_t)(t + 3) * DGG);

            cur = nxt;
            if (havepf) nxt = pf;
        }
        __syncthreads();
        if (j == 0) {
            __threadfence();
            st_rel(&g_prog[b], TT);
        }
        return;
    }

    // ======================= worker role: encoder, then head =======================
    int hb = blockIdx.x - BB;       // 0..83
    const int NT = 384;

    // ---- encoder phase ----
    for (int i = tid; i < 4096; i += NT) smem[E_W1 + i] = stem_w[i];
    for (int i = tid; i < 12288; i += NT) {
        int o = i & 63, ik = i >> 6;
        smem[E_CW + i] = conv_w[o * 192 + ik];
    }
    for (int i = tid; i < 24576; i += NT) {
        int h = i % 384, d = i / 384;
        smem[E_WIH + i] = w_ih[h * 64 + d];
    }
    if (tid < 64) { smem[E_SB + tid] = stem_b[tid]; smem[E_CB + tid] = conv_b[tid]; }
    if (tid >= 64 && tid < 448) smem[E_BIH + tid - 64] = b_ih[tid - 64];
    __syncthreads();

    for (int tau = hb; tau < 4096; tau += WCTAS) {
        int b = tau & 63;
        int t0 = (tau >> 6) << 6;        // t-major: all b for each 64-t block first

        // masked X load (raw-width dispatch) + canonical mask writeback (interior rows)
        for (int i = tid; i < 66 * 64; i += NT) {
            int row = i >> 6, f = i & 63;
            int t = t0 - 1 + row;
            float v = 0.f;
            if (t >= 0 && t < TT) {
                size_t gi = ((size_t)b * TT + t) * FF + f;
                unsigned mm;
                if (bF) mm = m8[gi];
                else if (hF) mm = m16[gi];
                else mm = m32[gi];
                v = mm ? 0.f : x[gi];
                if (row >= 1 && row < 65) g_mask[gi] = (unsigned char)(mm ? 1 : 0);
            }
            smem[E_X + i] = v;
        }
        __syncthreads();

        // stem GEMM + GELU (FFMA2); boundary rows zeroed
        for (int q = tid; q < 66 * 16; q += NT) {
            int i = q >> 4, d4 = (q & 15) << 2;
            int t = t0 - 1 + i;
            const u64* bp = (const u64*)&smem[E_SB + d4];
            u64 a0 = bp[0], a1 = bp[1];
            const float* xr = &smem[E_X + i * 64];
            #pragma unroll 16
            for (int f = 0; f < 64; f++) {
                float xv = xr[f];
                u64 x2 = pk2(xv, xv);
                const u64* ww = (const u64*)&smem[E_W1 + f * 64 + d4];
                a0 = fma2(x2, ww[0], a0);
                a1 = fma2(x2, ww[1], a1);
            }
            bool valid = (t >= 0) && (t < TT);
            float2 v0 = upk2(a0), v1 = upk2(a1);
            float4 r;
            r.x = valid ? gelu_exact(v0.x) : 0.f;
            r.y = valid ? gelu_exact(v0.y) : 0.f;
            r.z = valid ? gelu_exact(v1.x) : 0.f;
            r.w = valid ? gelu_exact(v1.y) : 0.f;
            *(float4*)&smem[E_H0 + i * 64 + d4] = r;
        }
        __syncthreads();

        // conv1d k=3 + GELU (FFMA2)
        for (int q = tid; q < 64 * 16; q += NT) {
            int tl = q >> 4, o4 = (q & 15) << 2;
            const u64* bp = (const u64*)&smem[E_CB + o4];
            u64 a0 = bp[0], a1 = bp[1];
            const float* h0a = &smem[E_H0 + tl * 64];
            const float* h0b = h0a + 64;
            const float* h0c = h0a + 128;
            #pragma unroll 8
            for (int i = 0; i < 64; i++) {
                u64 p0 = pk2(h0a[i], h0a[i]);
                u64 p1 = pk2(h0b[i], h0b[i]);
                u64 p2 = pk2(h0c[i], h0c[i]);
                const u64* w0 = (const u64*)&smem[E_CW + (i * 3 + 0) * 64 + o4];
                const u64* w1 = (const u64*)&smem[E_CW + (i * 3 + 1) * 64 + o4];
                const u64* w2 = (const u64*)&smem[E_CW + (i * 3 + 2) * 64 + o4];
                a0 = fma2(p0, w0[0], fma2(p1, w1[0], fma2(p2, w2[0], a0)));
                a1 = fma2(p0, w0[1], fma2(p1, w1[1], fma2(p2, w2[1], a1)));
            }
            float2 v0 = upk2(a0), v1 = upk2(a1);
            float* h1 = &smem[E_H1 + tl * 65 + o4];
            h1[0] = gelu_exact(v0.x);
            h1[1] = gelu_exact(v0.y);
            h1[2] = gelu_exact(v1.x);
            h1[3] = gelu_exact(v1.y);
        }
        __syncthreads();

        // gx GEMM (FFMA2) -> transposed store [b][h][t]
        for (int task = tid; task < 64 * 48; task += NT) {
            int tl = task & 63;
            int h8 = (task >> 6) << 3;
            u64 a0 = *(const u64*)&smem[E_BIH + h8];
            u64 a1 = *(const u64*)&smem[E_BIH + h8 + 2];
            u64 a2 = *(const u64*)&smem[E_BIH + h8 + 4];
            u64 a3 = *(const u64*)&smem[E_BIH + h8 + 6];
            const float* h1p = &smem[E_H1 + tl * 65];
            #pragma unroll 16
            for (int d = 0; d < 64; d++) {
                float hv = h1p[d];
                u64 h2 = pk2(hv, hv);
                const u64* ww = (const u64*)&smem[E_WIH + d * 384 + h8];
                a0 = fma2(h2, ww[0], a0);
                a1 = fma2(h2, ww[1], a1);
                a2 = fma2(h2, ww[2], a2);
                a3 = fma2(h2, ww[3], a3);
            }
            float2 r0 = upk2(a0), r1 = upk2(a1), r2 = upk2(a2), r3 = upk2(a3);
            float* gp = g_gx_buf + ((size_t)b * G3 + h8) * TT + (t0 + tl);
            gp[0]              = r0.x;
            gp[(size_t)TT]     = r0.y;
            gp[(size_t)2 * TT] = r1.x;
            gp[(size_t)3 * TT] = r1.y;
            gp[(size_t)4 * TT] = r2.x;
            gp[(size_t)5 * TT] = r2.y;
            gp[(size_t)6 * TT] = r3.x;
            gp[(size_t)7 * TT] = r3.y;
        }
        __syncthreads();
        if (tid == 0) {
            __threadfence();
            st_rel(&g_tiledone[tau], 1);
        }
    }

    // ---- head phase ----
    __syncthreads();
    if (tid >= 256) return;           // warps 8-11 exit whole

    double* sred = (double*)(smem + H_TOT);          // 256 doubles
    int* tileSlot = (int*)(smem + H_TOT + 512);

    for (int i = tid; i < 16384; i += 256) smem[H_W1 + i] = h1_w[i];
    for (int i = tid; i < 16384; i += 256) smem[H_W2 + i] = h2_w[i];
    for (int i = tid; i < 8192; i += 256) smem[H_W3 + i] = h3_w[i];
    if (tid < 128) { smem[H_B1 + tid] = h1_b[tid]; smem[H_B2 + tid] = h2_b[tid]; }
    if (tid >= 128 && tid < 192) smem[H_B3 + tid - 128] = h3_b[tid - 128];
    if (tid == 0) spin_ge(&g_statsctr, BB);          // all stats partials in
    __syncthreads();
    if (tid < 64) {
        double N = (double)(BB * TT);
        double mean = g_sum[tid] / N;
        double var = (g_sumsq[tid] - N * mean * mean) / (N - 1.0);
        double sd = sqrt(var) + 1e-8;
        smem[H_INV + tid] = (float)(1.0 / (sd * sd));
    }
    __syncthreads();

    float lacc = 0.f;

    while (true) {
        if (tid == 0) *tileSlot = atomicAdd(&g_headctr, 1);
        __syncthreads();
        int tile = *tileSlot;
        __syncthreads();
        if (tile >= BB * (TT / 32)) break;
        int b = tile & 63;
        int t0 = (tile >> 6) << 5;

        if (tid == 0) spin_ge(&g_prog[b], t0 + 32);
        __syncthreads();

        // load z transposed [k][t]
        for (int i = tid; i < 4096; i += 256) {
            int k = i & 127, t = i >> 7;
            smem[H_ZB + k * 34 + t] = g_z_buf[((size_t)b * TT + t0 + t) * DGG + k];
        }
        __syncthreads();

        // layer1
        {
            int o = tid & 127, g = tid >> 7;
            float bo = smem[H_B1 + o];
            u64 A[8];
            #pragma unroll
            for (int p = 0; p < 8; p++) A[p] = pk2(bo, bo);
            #pragma unroll 4
            for (int k = 0; k < 128; k++) {
                float wv = smem[H_W1 + k * 128 + o];
                u64 w2 = pk2(wv, wv);
                const float* zr = &smem[H_ZB + k * 34 + g * 16];
                #pragma unroll
                for (int p = 0; p < 8; p++) A[p] = fma2(*(const u64*)(zr + 2 * p), w2, A[p]);
            }
            float* rr = &smem[H_RB + o * 34 + g * 16];
            #pragma unroll
            for (int p = 0; p < 8; p++) {
                float2 v = upk2(A[p]);
                rr[2 * p]     = gelu_exact(v.x);
                rr[2 * p + 1] = gelu_exact(v.y);
            }
        }
        __syncthreads();

        // layer2
        {
            int o = tid & 127, g = tid >> 7;
            float bo = smem[H_B2 + o];
            u64 A[8];
            #pragma unroll
            for (int p = 0; p < 8; p++) A[p] = pk2(bo, bo);
            #pragma unroll 4
            for (int k = 0; k < 128; k++) {
                float wv = smem[H_W2 + k * 128 + o];
                u64 w2 = pk2(wv, wv);
                const float* zr = &smem[H_RB + k * 34 + g * 16];
                #pragma unroll
                for (int p = 0; p < 8; p++) A[p] = fma2(*(const u64*)(zr + 2 * p), w2, A[p]);
            }
            float* rr = &smem[H_ZB + o * 34 + g * 16];
            #pragma unroll
            for (int p = 0; p < 8; p++) {
                float2 v = upk2(A[p]);
                rr[2 * p]     = gelu_exact(v.x);
                rr[2 * p + 1] = gelu_exact(v.y);
            }
        }
        __syncthreads();

        // layer3 + loss
        {
            int o = tid & 63, g = tid >> 6;
            float bo = smem[H_B3 + o];
            float invs = smem[H_INV + o];
            u64 A[4];
            #pragma unroll
            for (int p = 0; p < 4; p++) A[p] = pk2(bo, bo);
            #pragma unroll 4
            for (int k = 0; k < 128; k++) {
                float wv = smem[H_W3 + k * 64 + o];
                u64 w2 = pk2(wv, wv);
                const float* zr = &smem[H_ZB + k * 34 + g * 8];
                #pragma unroll
                for (int p = 0; p < 4; p++) A[p] = fma2(*(const u64*)(zr + 2 * p), w2, A[p]);
            }
            #pragma unroll
            for (int p = 0; p < 4; p++) {
                int t = t0 + g * 8 + 2 * p;
                size_t gi = ((size_t)b * TT + t) * FF + o;
                float2 v = upk2(A[p]);
                float d0 = v.x - x[gi];
                float d1 = v.y - x[gi + FF];
                if (g_mask[gi])      lacc = fmaf(d0 * d0, invs, lacc);
                if (g_mask[gi + FF]) lacc = fmaf(d1 * d1, invs, lacc);
            }
        }
        __syncthreads();    // ZB readers done before next tile rewrites
    }

    sred[tid] = (double)lacc;
    __syncthreads();
    for (int s = 128; s > 0; s >>= 1) {
        if (tid < s) sred[tid] += sred[tid + s];
        __syncthreads();
    }
    if (tid == 0) atomicAdd(&g_loss, sred[0]);
}

// ---------------- K3: finalize ----------------
__global__ void k_final(float* out) {
    double denom = g_mcnt > 1.0 ? g_mcnt : 1.0;
    out[0] = (float)(g_loss / denom);
}

// ---------------- launch ----------------
extern "C" void kernel_launch(void* const* d_in, const int* in_sizes, int n_in,
                              void* d_out, int out_size) {
    const float* x          = (const float*)d_in[0];
    const void*  fm         = (const void*)d_in[1];
    const float* stem_w     = (const float*)d_in[2];
    const float* stem_b     = (const float*)d_in[3];
    const float* conv_w     = (const float*)d_in[4];
    const float* conv_b     = (const float*)d_in[5];
    const float* gru_w_ih   = (const float*)d_in[6];
    const float* gru_w_hh   = (const float*)d_in[7];
    const float* gru_b_ih   = (const float*)d_in[8];
    const float* gru_b_hh   = (const float*)d_in[9];
    const float* h1_w       = (const float*)d_in[10];
    const float* h1_b       = (const float*)d_in[11];
    const float* h2_w       = (const float*)d_in[12];
    const float* h2_b       = (const float*)d_in[13];
    const float* h3_w       = (const float*)d_in[14];
    const float* h3_b       = (const float*)d_in[15];
    float* out = (float*)d_out;

    cudaFuncSetAttribute(k_gruhead, cudaFuncAttributeMaxDynamicSharedMemorySize, SMEM_BYTES);

    k_init<<<1, 256>>>();
    k_init2<<<8, 512>>>();
    k_probe<<<512, 256>>>((const unsigned int*)fm);
    k_gruhead<<<BB + WCTAS, 384, SMEM_BYTES>>>(
        x, fm, stem_w, stem_b, conv_w, conv_b, gru_w_ih, gru_b_ih,
        gru_w_hh, gru_b_hh, h1_w, h1_b, h2_w, h2_b, h3_w, h3_b);
    k_final<<<1, 1>>>(out);
}